// round 3
// baseline (speedup 1.0000x reference)
#include <cuda_runtime.h>
#include <math.h>
#include <stdint.h>

// ---------------------------------------------------------------------------
// GPT-2-style MQA transformer forward, fp32.
//   L=4 layers, H=1024, N=16 heads, D=64, I=4096, V=50257, B=2, S=2048.
// All GEMMs are C[M,N] = A[M,K] @ W[N,K]^T (+bias [+gelu] [+residual]).
// ---------------------------------------------------------------------------

#define LL 4
#define HH 1024
#define DD 64
#define NHEAD 16
#define II 4096
#define BB 2
#define SS 2048
#define QKVW (HH + 2 * DD)      // 1152
#define MTOK (BB * SS)          // 4096
#define LN_EPS 1e-5f

// ------------------------- scratch (static device mem) ---------------------
__device__ float g_h  [(size_t)MTOK * HH];     // residual stream
__device__ float g_x  [(size_t)MTOK * HH];     // LN output / GEMM input
__device__ float g_qkv[(size_t)MTOK * QKVW];   // qkv projection
__device__ float g_att[(size_t)MTOK * HH];     // attention output
__device__ float g_mlp[(size_t)MTOK * II];     // MLP hidden

// ----------------------------- embedding -----------------------------------
__global__ void embed_kernel(const int* __restrict__ ids,
                             const int* __restrict__ pos,
                             const float* __restrict__ wte,
                             const float* __restrict__ wpe,
                             float* __restrict__ out)
{
    int row = blockIdx.x;                 // token index 0..4095
    int t   = threadIdx.x;                // 256 threads, HH/4 = 256 float4
    int id  = ids[row];
    int p   = pos[row];
    const float4* a = (const float4*)(wte + (size_t)id * HH);
    const float4* b = (const float4*)(wpe + (size_t)p  * HH);
    float4 va = a[t], vb = b[t];
    float4 o  = make_float4(va.x + vb.x, va.y + vb.y, va.z + vb.z, va.w + vb.w);
    ((float4*)(out + (size_t)row * HH))[t] = o;
}

// ----------------------------- layernorm ------------------------------------
__global__ void ln_kernel(const float* __restrict__ x,
                          const float* __restrict__ w,
                          const float* __restrict__ b,
                          float* __restrict__ y)
{
    int row = blockIdx.x;
    int t   = threadIdx.x;                // 256 threads, one float4 each
    __shared__ float red[256];

    float4 v = ((const float4*)(x + (size_t)row * HH))[t];
    red[t] = v.x + v.y + v.z + v.w;
    __syncthreads();
    #pragma unroll
    for (int o = 128; o > 0; o >>= 1) { if (t < o) red[t] += red[t + o]; __syncthreads(); }
    float mu = red[0] * (1.0f / HH);
    __syncthreads();

    float dx = v.x - mu, dy = v.y - mu, dz = v.z - mu, dw = v.w - mu;
    red[t] = dx*dx + dy*dy + dz*dz + dw*dw;
    __syncthreads();
    #pragma unroll
    for (int o = 128; o > 0; o >>= 1) { if (t < o) red[t] += red[t + o]; __syncthreads(); }
    float rstd = rsqrtf(red[0] * (1.0f / HH) + LN_EPS);

    float4 ww = ((const float4*)w)[t];
    float4 bb2 = ((const float4*)b)[t];
    float4 o4 = make_float4(dx * rstd * ww.x + bb2.x,
                            dy * rstd * ww.y + bb2.y,
                            dz * rstd * ww.z + bb2.z,
                            dw * rstd * ww.w + bb2.w);
    ((float4*)(y + (size_t)row * HH))[t] = o4;
}

// ------------------------------- SGEMM --------------------------------------
// C[M,N] = A[M,K] @ W[N,K]^T + bias  [-> gelu] [+ resid].  M,N %128==0, K%8==0.
template<bool RESID, bool GELU>
__global__ __launch_bounds__(256)
void gemm_kernel(const float* __restrict__ A, const float* __restrict__ W,
                 const float* __restrict__ bias, const float* __restrict__ resid,
                 float* __restrict__ C, int M, int N, int K)
{
    __shared__ float As[8][128];
    __shared__ float Bs[8][128];

    int tid = threadIdx.x;
    int bm  = blockIdx.y * 128;
    int bn  = blockIdx.x * 128;

    int lr = tid >> 1;            // 0..127 (row within tile)
    int lk = (tid & 1) * 4;       // 0 or 4 (k offset)
    const float* Ab = A + (size_t)(bm + lr) * K + lk;
    const float* Wb = W + (size_t)(bn + lr) * K + lk;

    int tx = tid & 15;            // 0..15  -> 8 output cols
    int ty = tid >> 4;            // 0..15  -> 8 output rows

    float acc[8][8];
    #pragma unroll
    for (int i = 0; i < 8; i++)
        #pragma unroll
        for (int j = 0; j < 8; j++) acc[i][j] = 0.0f;

    int T = K >> 3;
    float4 ra = *(const float4*)Ab;
    float4 rb = *(const float4*)Wb;

    for (int t = 0; t < T; ++t) {
        As[lk + 0][lr] = ra.x; As[lk + 1][lr] = ra.y;
        As[lk + 2][lr] = ra.z; As[lk + 3][lr] = ra.w;
        Bs[lk + 0][lr] = rb.x; Bs[lk + 1][lr] = rb.y;
        Bs[lk + 2][lr] = rb.z; Bs[lk + 3][lr] = rb.w;
        __syncthreads();

        if (t + 1 < T) {
            ra = *(const float4*)(Ab + (size_t)(t + 1) * 8);
            rb = *(const float4*)(Wb + (size_t)(t + 1) * 8);
        }

        #pragma unroll
        for (int k = 0; k < 8; ++k) {
            float4 a0 = *(const float4*)&As[k][ty * 8];
            float4 a1 = *(const float4*)&As[k][ty * 8 + 4];
            float4 b0 = *(const float4*)&Bs[k][tx * 8];
            float4 b1 = *(const float4*)&Bs[k][tx * 8 + 4];
            float af[8] = {a0.x, a0.y, a0.z, a0.w, a1.x, a1.y, a1.z, a1.w};
            float bf[8] = {b0.x, b0.y, b0.z, b0.w, b1.x, b1.y, b1.z, b1.w};
            #pragma unroll
            for (int i = 0; i < 8; i++)
                #pragma unroll
                for (int j = 0; j < 8; j++)
                    acc[i][j] += af[i] * bf[j];
        }
        __syncthreads();
    }

    #pragma unroll
    for (int i = 0; i < 8; i++) {
        int row = bm + ty * 8 + i;
        float*       Crow = C + (size_t)row * N + bn + tx * 8;
        const float* Rrow = RESID ? (resid + (size_t)row * N + bn + tx * 8) : nullptr;
        #pragma unroll
        for (int j = 0; j < 8; j++) {
            float v = acc[i][j] + bias[bn + tx * 8 + j];
            if (GELU)  v = 0.5f * v * (1.0f + erff(v * 0.70710678118654752f));
            if (RESID) v += Rrow[j];
            Crow[j] = v;
        }
    }
}

// ------------------------------ attention -----------------------------------
// MQA causal flash attention. One block = 128 query rows of one head of one
// batch; one thread = one query row (q & acc in registers). K/V single head,
// tiles of 64 keys staged in smem, broadcast LDS.128 reads.
__global__ __launch_bounds__(128)
void attn_kernel(const float* __restrict__ qkv, float* __restrict__ out)
{
    __shared__ float Ks[64][64];
    __shared__ float Vs[64][64];

    int q0    = blockIdx.x * 128;
    int head  = blockIdx.y;
    int batch = blockIdx.z;
    int tid   = threadIdx.x;
    int qi    = q0 + tid;

    const float* base = qkv + (size_t)batch * SS * QKVW;

    // load query row, fold in 1/sqrt(D) = 0.125 (unscale cancels exactly)
    float q[64];
    const float* qrow = base + (size_t)qi * QKVW + head * DD;
    #pragma unroll
    for (int d = 0; d < 64; d += 4) {
        float4 v = *(const float4*)(qrow + d);
        q[d] = v.x * 0.125f; q[d+1] = v.y * 0.125f;
        q[d+2] = v.z * 0.125f; q[d+3] = v.w * 0.125f;
    }

    float acc[64];
    #pragma unroll
    for (int d = 0; d < 64; d++) acc[d] = 0.0f;
    float m = -INFINITY, l = 0.0f;

    int nt = q0 / 64 + 2;   // key tiles covering keys <= q0+127
    for (int kt = 0; kt < nt; ++kt) {
        int k0 = kt * 64;

        // cooperative coalesced K/V tile load (64 rows x 64 floats each)
        for (int f = tid; f < 1024; f += 128) {
            int j  = f >> 4;
            int dd = (f & 15) << 2;
            const float* kr = base + (size_t)(k0 + j) * QKVW + HH;
            *(float4*)&Ks[j][dd] = *(const float4*)(kr + dd);
            *(float4*)&Vs[j][dd] = *(const float4*)(kr + DD + dd);
        }
        __syncthreads();

        #pragma unroll 1
        for (int sb = 0; sb < 64; sb += 16) {
            float s[16];
            float mt = -INFINITY;
            #pragma unroll
            for (int jj = 0; jj < 16; ++jj) {
                int j = sb + jj;
                float dot = 0.0f;
                #pragma unroll
                for (int d = 0; d < 64; d += 4) {
                    float4 kk = *(const float4*)&Ks[j][d];
                    dot += q[d] * kk.x + q[d+1] * kk.y
                         + q[d+2] * kk.z + q[d+3] * kk.w;
                }
                s[jj] = (k0 + j <= qi) ? dot : -INFINITY;
                mt = fmaxf(mt, s[jj]);
            }
            if (mt != -INFINITY) {          // skip fully-masked subtiles
                float mn = fmaxf(m, mt);
                float c  = __expf(m - mn);  // m = -inf on first pass -> 0
                float psum = 0.0f;
                #pragma unroll
                for (int jj = 0; jj < 16; ++jj) {
                    s[jj] = __expf(s[jj] - mn);
                    psum += s[jj];
                }
                l = l * c + psum;
                #pragma unroll
                for (int d = 0; d < 64; d++) acc[d] *= c;
                #pragma unroll
                for (int jj = 0; jj < 16; ++jj) {
                    float pj = s[jj];
                    #pragma unroll
                    for (int d = 0; d < 64; d += 4) {
                        float4 vv = *(const float4*)&Vs[sb + jj][d];
                        acc[d]   += pj * vv.x; acc[d+1] += pj * vv.y;
                        acc[d+2] += pj * vv.z; acc[d+3] += pj * vv.w;
                    }
                }
                m = mn;
            }
        }
        __syncthreads();
    }

    float inv = 1.0f / l;
    float* orow = out + (size_t)(batch * SS + qi) * HH + head * DD;
    #pragma unroll
    for (int d = 0; d < 64; d += 4) {
        float4 v = make_float4(acc[d] * inv, acc[d+1] * inv,
                               acc[d+2] * inv, acc[d+3] * inv);
        *(float4*)(orow + d) = v;
    }
}

// ------------------------------- driver -------------------------------------
extern "C" void kernel_launch(void* const* d_in, const int* in_sizes, int n_in,
                              void* d_out, int out_size)
{
    const int*   ids     = (const int*)  d_in[0];
    const int*   pos     = (const int*)  d_in[1];
    const float* wte     = (const float*)d_in[2];
    const float* wpe     = (const float*)d_in[3];
    const float* ln1_w   = (const float*)d_in[4];
    const float* ln1_b   = (const float*)d_in[5];
    const float* cattn_w = (const float*)d_in[6];
    const float* cattn_b = (const float*)d_in[7];
    const float* cproj_w = (const float*)d_in[8];
    const float* cproj_b = (const float*)d_in[9];
    const float* ln2_w   = (const float*)d_in[10];
    const float* ln2_b   = (const float*)d_in[11];
    const float* fc_w    = (const float*)d_in[12];
    const float* fc_b    = (const float*)d_in[13];
    const float* mproj_w = (const float*)d_in[14];
    const float* mproj_b = (const float*)d_in[15];
    const float* lnf_w   = (const float*)d_in[16];
    const float* lnf_b   = (const float*)d_in[17];
    float* out = (float*)d_out;

    float *h, *x, *qkv, *att, *mlp;
    cudaGetSymbolAddress((void**)&h,   g_h);
    cudaGetSymbolAddress((void**)&x,   g_x);
    cudaGetSymbolAddress((void**)&qkv, g_qkv);
    cudaGetSymbolAddress((void**)&att, g_att);
    cudaGetSymbolAddress((void**)&mlp, g_mlp);

    embed_kernel<<<MTOK, 256>>>(ids, pos, wte, wpe, h);

    for (int l = 0; l < LL; ++l) {
        // x = LN1(h)
        ln_kernel<<<MTOK, 256>>>(h, ln1_w + (size_t)l * HH, ln1_b + (size_t)l * HH, x);
        // qkv = x @ cattn_w^T + cattn_b
        gemm_kernel<false, false><<<dim3(QKVW / 128, MTOK / 128), 256>>>(
            x, cattn_w + (size_t)l * QKVW * HH, cattn_b + (size_t)l * QKVW,
            nullptr, qkv, MTOK, QKVW, HH);
        // att = causal MQA softmax attention
        attn_kernel<<<dim3(SS / 128, NHEAD, BB), 128>>>(qkv, att);
        // h = h + att @ cproj_w^T + cproj_b
        gemm_kernel<true, false><<<dim3(HH / 128, MTOK / 128), 256>>>(
            att, cproj_w + (size_t)l * HH * HH, cproj_b + (size_t)l * HH,
            h, h, MTOK, HH, HH);
        // x = LN2(h)
        ln_kernel<<<MTOK, 256>>>(h, ln2_w + (size_t)l * HH, ln2_b + (size_t)l * HH, x);
        // mlp = gelu(x @ fc_w^T + fc_b)
        gemm_kernel<false, true><<<dim3(II / 128, MTOK / 128), 256>>>(
            x, fc_w + (size_t)l * II * HH, fc_b + (size_t)l * II,
            nullptr, mlp, MTOK, II, HH);
        // h = h + mlp @ mproj_w^T + mproj_b
        gemm_kernel<true, false><<<dim3(HH / 128, MTOK / 128), 256>>>(
            mlp, mproj_w + (size_t)l * HH * II, mproj_b + (size_t)l * HH,
            h, h, MTOK, HH, II);
    }

    // out = LNf(h)
    ln_kernel<<<MTOK, 256>>>(h, lnf_w, lnf_b, out);
}

// round 6
// speedup vs baseline: 1.4349x; 1.4349x over previous
#include <cuda_runtime.h>
#include <cuda_bf16.h>
#include <math.h>
#include <stdint.h>

// ---------------------------------------------------------------------------
// GPT-2-style MQA transformer forward.
//   L=4, H=1024, N=16 heads, D=64, I=4096, B=2, S=2048.
// GEMMs: warp-level mma.sync bf16 with 3-term fp32 split (portable sm_103).
// Attention: fp32 SIMT flash kernel.
// ---------------------------------------------------------------------------

#define LL 4
#define HH 1024
#define DD 64
#define NHEAD 16
#define II 4096
#define BB 2
#define SS 2048
#define QKVW (HH + 2 * DD)      // 1152
#define MTOK (BB * SS)          // 4096
#define LN_EPS 1e-5f

// ------------------------- scratch (static device mem) ---------------------
__device__ float g_h  [(size_t)MTOK * HH];
__device__ float g_x  [(size_t)MTOK * HH];
__device__ float g_qkv[(size_t)MTOK * QKVW];
__device__ float g_att[(size_t)MTOK * HH];
__device__ float g_mlp[(size_t)MTOK * II];

// ----------------------------- PTX helpers ---------------------------------
__device__ __forceinline__ uint32_t smem_u32(const void* p) {
    uint32_t a;
    asm("{ .reg .u64 t; cvta.to.shared.u64 t, %1; cvt.u32.u64 %0, t; }"
        : "=r"(a) : "l"(p));
    return a;
}
__device__ __forceinline__ void ldsm4(uint32_t* r, uint32_t addr) {
    asm volatile("ldmatrix.sync.aligned.m8n8.x4.shared.b16 {%0,%1,%2,%3}, [%4];"
        : "=r"(r[0]), "=r"(r[1]), "=r"(r[2]), "=r"(r[3]) : "r"(addr));
}
__device__ __forceinline__ void mma_bf16(float* d, const uint32_t* a,
                                         uint32_t b0, uint32_t b1) {
    asm volatile("mma.sync.aligned.m16n8k16.row.col.f32.bf16.bf16.f32 "
        "{%0,%1,%2,%3}, {%4,%5,%6,%7}, {%8,%9}, {%0,%1,%2,%3};"
        : "+f"(d[0]), "+f"(d[1]), "+f"(d[2]), "+f"(d[3])
        : "r"(a[0]), "r"(a[1]), "r"(a[2]), "r"(a[3]), "r"(b0), "r"(b1));
}

// split one fp32 pair into packed bf16 hi pair + lo pair
__device__ __forceinline__ void split_pair(float x, float y,
                                           uint32_t& hi, uint32_t& lo) {
    __nv_bfloat16 hx = __float2bfloat16(x), hy = __float2bfloat16(y);
    float lx = x - __bfloat162float(hx);
    float ly = y - __bfloat162float(hy);
    __nv_bfloat16 gx = __float2bfloat16(lx), gy = __float2bfloat16(ly);
    hi = (uint32_t)*reinterpret_cast<unsigned short*>(&hx)
       | ((uint32_t)*reinterpret_cast<unsigned short*>(&hy) << 16);
    lo = (uint32_t)*reinterpret_cast<unsigned short*>(&gx)
       | ((uint32_t)*reinterpret_cast<unsigned short*>(&gy) << 16);
}

// ----------------------------- embedding -----------------------------------
__global__ void embed_kernel(const int* __restrict__ ids,
                             const int* __restrict__ pos,
                             const float* __restrict__ wte,
                             const float* __restrict__ wpe,
                             float* __restrict__ out)
{
    int row = blockIdx.x;
    int t   = threadIdx.x;
    int id  = ids[row];
    int p   = pos[row];
    const float4* a = (const float4*)(wte + (size_t)id * HH);
    const float4* b = (const float4*)(wpe + (size_t)p  * HH);
    float4 va = a[t], vb = b[t];
    ((float4*)(out + (size_t)row * HH))[t] =
        make_float4(va.x + vb.x, va.y + vb.y, va.z + vb.z, va.w + vb.w);
}

// ----------------------------- layernorm ------------------------------------
__global__ void ln_kernel(const float* __restrict__ x,
                          const float* __restrict__ w,
                          const float* __restrict__ b,
                          float* __restrict__ y)
{
    int row = blockIdx.x;
    int t   = threadIdx.x;
    __shared__ float red[256];

    float4 v = ((const float4*)(x + (size_t)row * HH))[t];
    red[t] = v.x + v.y + v.z + v.w;
    __syncthreads();
    #pragma unroll
    for (int o = 128; o > 0; o >>= 1) { if (t < o) red[t] += red[t + o]; __syncthreads(); }
    float mu = red[0] * (1.0f / HH);
    __syncthreads();

    float dx = v.x - mu, dy = v.y - mu, dz = v.z - mu, dw = v.w - mu;
    red[t] = dx*dx + dy*dy + dz*dz + dw*dw;
    __syncthreads();
    #pragma unroll
    for (int o = 128; o > 0; o >>= 1) { if (t < o) red[t] += red[t + o]; __syncthreads(); }
    float rstd = rsqrtf(red[0] * (1.0f / HH) + LN_EPS);

    float4 ww = ((const float4*)w)[t];
    float4 bb2 = ((const float4*)b)[t];
    ((float4*)(y + (size_t)row * HH))[t] =
        make_float4(dx * rstd * ww.x + bb2.x, dy * rstd * ww.y + bb2.y,
                    dz * rstd * ww.z + bb2.z, dw * rstd * ww.w + bb2.w);
}

// ------------------------- bf16 split-3 MMA GEMM ----------------------------
// C[M,N] = A[M,K] @ W[N,K]^T + bias [-> gelu] [+ resid].  M,N%128==0, K%32==0.
// CTA: 128x128 tile, 256 threads (8 warps, 4x2 -> 32x64 per warp).
// K chunks of 32 floats; each chunk split into bf16 hi/lo tiles in SMEM.
// SMEM tile layout: [128 rows][4 x 16B k-chunks], chunk' = chunk ^ ((row>>1)&3)
//   -> conflict-free for STS.128 writer and all ldmatrix phases.
// NOTE: both A and W are row-major with K contiguous -> BOTH use non-trans
// ldmatrix (mma B frag lane i = W[i/4][2(i%4)+{0,1}] = non-trans distribution).
#define TILE_BYTES 8192                     // 128 x 32 bf16
#define STAGE_BYTES (4 * TILE_BYTES)        // Ah, Al, Wh, Wl
#define GEMM_SMEM (2 * STAGE_BYTES)         // 65536

template<bool RESID, bool GELU>
__global__ __launch_bounds__(256, 1)
void gemm_mma(const float* __restrict__ A, const float* __restrict__ W,
              const float* __restrict__ bias, const float* __restrict__ resid,
              float* __restrict__ C, int M, int Nn, int K)
{
    extern __shared__ char smem[];
    uint32_t sb = smem_u32(smem);

    int tid  = threadIdx.x;
    int lane = tid & 31;
    int wid  = tid >> 5;
    int wm   = wid >> 1;          // 0..3 -> 32 m-rows each
    int wn   = wid & 1;           // 0..1 -> 64 n-cols each
    int bm   = blockIdx.y * 128;
    int bn   = blockIdx.x * 128;

    // per-thread writer task coords: 4 tasks (2 for A, 2 for W)
    // task e in [0,512): row = e>>2, kchunk = e&3 (8 floats each)
    int eA0 = tid, eA1 = tid + 256;
    float4 pre[8];                 // prefetch regs: A t0, A t1, W t0, W t1 (2 f4 each)

    auto load_chunk = [&](int kb) {
        {
            const float* p = A + (size_t)(bm + (eA0 >> 2)) * K + kb + (eA0 & 3) * 8;
            pre[0] = *(const float4*)p; pre[1] = *(const float4*)(p + 4);
        }
        {
            const float* p = A + (size_t)(bm + (eA1 >> 2)) * K + kb + (eA1 & 3) * 8;
            pre[2] = *(const float4*)p; pre[3] = *(const float4*)(p + 4);
        }
        {
            const float* p = W + (size_t)(bn + (eA0 >> 2)) * K + kb + (eA0 & 3) * 8;
            pre[4] = *(const float4*)p; pre[5] = *(const float4*)(p + 4);
        }
        {
            const float* p = W + (size_t)(bn + (eA1 >> 2)) * K + kb + (eA1 & 3) * 8;
            pre[6] = *(const float4*)p; pre[7] = *(const float4*)(p + 4);
        }
    };

    auto store_split = [&](int stage) {
        uint32_t base = sb + stage * STAGE_BYTES;
        #pragma unroll
        for (int s = 0; s < 4; s++) {       // 0,1: A tasks; 2,3: W tasks
            int e   = (s & 1) ? eA1 : eA0;
            int row = e >> 2;
            int kc  = e & 3;
            uint32_t off = (uint32_t)row * 64 + ((kc ^ ((row >> 1) & 3)) << 4);
            uint32_t hbase = base + (s >= 2 ? 2 * TILE_BYTES : 0);
            float4 f0 = pre[s * 2], f1 = pre[s * 2 + 1];
            uint4 Hi, Lo;
            split_pair(f0.x, f0.y, Hi.x, Lo.x);
            split_pair(f0.z, f0.w, Hi.y, Lo.y);
            split_pair(f1.x, f1.y, Hi.z, Lo.z);
            split_pair(f1.z, f1.w, Hi.w, Lo.w);
            asm volatile("st.shared.v4.b32 [%0], {%1,%2,%3,%4};"
                :: "r"(hbase + off), "r"(Hi.x), "r"(Hi.y), "r"(Hi.z), "r"(Hi.w) : "memory");
            asm volatile("st.shared.v4.b32 [%0], {%1,%2,%3,%4};"
                :: "r"(hbase + TILE_BYTES + off), "r"(Lo.x), "r"(Lo.y), "r"(Lo.z), "r"(Lo.w) : "memory");
        }
    };

    // consumer lane geometry
    int maBase = (lane & 7) + ((lane >> 3) & 1) * 8;   // A: tile-relative m
    int kAhalf = lane >> 4;                            // A: k16-chunk select
    int nbBase = (lane & 7) + ((lane >> 4) & 1) * 8;   // B: tile-relative n
    int kBhalf = (lane >> 3) & 1;                      // B: k16-chunk select

    float acc[2][8][4];
    #pragma unroll
    for (int i = 0; i < 2; i++)
        #pragma unroll
        for (int j = 0; j < 8; j++)
            #pragma unroll
            for (int q = 0; q < 4; q++) acc[i][j][q] = 0.0f;

    const int T = K >> 5;
    load_chunk(0);

    for (int t = 0; t < T; ++t) {
        int stage = t & 1;
        store_split(stage);
        __syncthreads();
        if (t + 1 < T) load_chunk((t + 1) << 5);

        uint32_t Ab = sb + stage * STAGE_BYTES;
        uint32_t Wb = Ab + 2 * TILE_BYTES;

        #pragma unroll
        for (int kt = 0; kt < 2; ++kt) {
            int kcA = kt * 2 + kAhalf;
            int kcB = kt * 2 + kBhalf;

            uint32_t ah[2][4], al[2][4];
            #pragma unroll
            for (int mi = 0; mi < 2; mi++) {
                int m = wm * 32 + mi * 16 + maBase;
                uint32_t off = (uint32_t)m * 64 + ((kcA ^ ((m >> 1) & 3)) << 4);
                ldsm4(ah[mi], Ab + off);
                ldsm4(al[mi], Ab + TILE_BYTES + off);
            }

            #pragma unroll
            for (int ni = 0; ni < 4; ni++) {
                int n = wn * 64 + ni * 16 + nbBase;
                uint32_t off = (uint32_t)n * 64 + ((kcB ^ ((n >> 1) & 3)) << 4);
                uint32_t bh[4], bl[4];
                ldsm4(bh, Wb + off);                 // non-trans: W[n][k] rows
                ldsm4(bl, Wb + TILE_BYTES + off);
                #pragma unroll
                for (int mi = 0; mi < 2; mi++) {
                    mma_bf16(acc[mi][ni * 2 + 0], ah[mi], bh[0], bh[1]);
                    mma_bf16(acc[mi][ni * 2 + 1], ah[mi], bh[2], bh[3]);
                    mma_bf16(acc[mi][ni * 2 + 0], ah[mi], bl[0], bl[1]);
                    mma_bf16(acc[mi][ni * 2 + 1], ah[mi], bl[2], bl[3]);
                    mma_bf16(acc[mi][ni * 2 + 0], al[mi], bh[0], bh[1]);
                    mma_bf16(acc[mi][ni * 2 + 1], al[mi], bh[2], bh[3]);
                }
            }
        }
        __syncthreads();
    }

    // ------------------------------ epilogue --------------------------------
    int g     = lane >> 2;
    int cpair = (lane & 3) * 2;
    #pragma unroll
    for (int mi = 0; mi < 2; mi++) {
        #pragma unroll
        for (int j = 0; j < 8; j++) {
            int col = bn + wn * 64 + (j >> 1) * 16 + (j & 1) * 8 + cpair;
            int r0  = bm + wm * 32 + mi * 16 + g;
            float b0 = bias[col], b1 = bias[col + 1];
            #pragma unroll
            for (int hrow = 0; hrow < 2; hrow++) {
                int row = r0 + hrow * 8;
                float v0 = acc[mi][j][hrow * 2 + 0] + b0;
                float v1 = acc[mi][j][hrow * 2 + 1] + b1;
                if (GELU) {
                    v0 = 0.5f * v0 * (1.0f + erff(v0 * 0.70710678118654752f));
                    v1 = 0.5f * v1 * (1.0f + erff(v1 * 0.70710678118654752f));
                }
                if (RESID) {
                    const float* rr = resid + (size_t)row * Nn + col;
                    v0 += rr[0]; v1 += rr[1];
                }
                *(float2*)(C + (size_t)row * Nn + col) = make_float2(v0, v1);
            }
        }
    }
}

// ------------------------------ attention -----------------------------------
__global__ __launch_bounds__(128)
void attn_kernel(const float* __restrict__ qkv, float* __restrict__ out)
{
    __shared__ float Ks[64][64];
    __shared__ float Vs[64][64];

    int q0    = blockIdx.x * 128;
    int head  = blockIdx.y;
    int batch = blockIdx.z;
    int tid   = threadIdx.x;
    int qi    = q0 + tid;

    const float* base = qkv + (size_t)batch * SS * QKVW;

    float q[64];
    const float* qrow = base + (size_t)qi * QKVW + head * DD;
    #pragma unroll
    for (int d = 0; d < 64; d += 4) {
        float4 v = *(const float4*)(qrow + d);
        q[d] = v.x * 0.125f; q[d+1] = v.y * 0.125f;
        q[d+2] = v.z * 0.125f; q[d+3] = v.w * 0.125f;
    }

    float acc[64];
    #pragma unroll
    for (int d = 0; d < 64; d++) acc[d] = 0.0f;
    float m = -INFINITY, l = 0.0f;

    int nt = q0 / 64 + 2;
    for (int kt = 0; kt < nt; ++kt) {
        int k0 = kt * 64;
        for (int f = tid; f < 1024; f += 128) {
            int j  = f >> 4;
            int dd = (f & 15) << 2;
            const float* kr = base + (size_t)(k0 + j) * QKVW + HH;
            *(float4*)&Ks[j][dd] = *(const float4*)(kr + dd);
            *(float4*)&Vs[j][dd] = *(const float4*)(kr + DD + dd);
        }
        __syncthreads();

        #pragma unroll 1
        for (int sb2 = 0; sb2 < 64; sb2 += 16) {
            float s[16];
            float mt = -INFINITY;
            #pragma unroll
            for (int jj = 0; jj < 16; ++jj) {
                int j = sb2 + jj;
                float dot = 0.0f;
                #pragma unroll
                for (int d = 0; d < 64; d += 4) {
                    float4 kk = *(const float4*)&Ks[j][d];
                    dot += q[d] * kk.x + q[d+1] * kk.y
                         + q[d+2] * kk.z + q[d+3] * kk.w;
                }
                s[jj] = (k0 + j <= qi) ? dot : -INFINITY;
                mt = fmaxf(mt, s[jj]);
            }
            if (mt != -INFINITY) {
                float mn = fmaxf(m, mt);
                float c  = __expf(m - mn);
                float psum = 0.0f;
                #pragma unroll
                for (int jj = 0; jj < 16; ++jj) {
                    s[jj] = __expf(s[jj] - mn);
                    psum += s[jj];
                }
                l = l * c + psum;
                #pragma unroll
                for (int d = 0; d < 64; d++) acc[d] *= c;
                #pragma unroll
                for (int jj = 0; jj < 16; ++jj) {
                    float pj = s[jj];
                    #pragma unroll
                    for (int d = 0; d < 64; d += 4) {
                        float4 vv = *(const float4*)&Vs[sb2 + jj][d];
                        acc[d]   += pj * vv.x; acc[d+1] += pj * vv.y;
                        acc[d+2] += pj * vv.z; acc[d+3] += pj * vv.w;
                    }
                }
                m = mn;
            }
        }
        __syncthreads();
    }

    float inv = 1.0f / l;
    float* orow = out + (size_t)(batch * SS + qi) * HH + head * DD;
    #pragma unroll
    for (int d = 0; d < 64; d += 4) {
        *(float4*)(orow + d) = make_float4(acc[d] * inv, acc[d+1] * inv,
                                           acc[d+2] * inv, acc[d+3] * inv);
    }
}

// ------------------------------- driver -------------------------------------
extern "C" void kernel_launch(void* const* d_in, const int* in_sizes, int n_in,
                              void* d_out, int out_size)
{
    const int*   ids     = (const int*)  d_in[0];
    const int*   pos     = (const int*)  d_in[1];
    const float* wte     = (const float*)d_in[2];
    const float* wpe     = (const float*)d_in[3];
    const float* ln1_w   = (const float*)d_in[4];
    const float* ln1_b   = (const float*)d_in[5];
    const float* cattn_w = (const float*)d_in[6];
    const float* cattn_b = (const float*)d_in[7];
    const float* cproj_w = (const float*)d_in[8];
    const float* cproj_b = (const float*)d_in[9];
    const float* ln2_w   = (const float*)d_in[10];
    const float* ln2_b   = (const float*)d_in[11];
    const float* fc_w    = (const float*)d_in[12];
    const float* fc_b    = (const float*)d_in[13];
    const float* mproj_w = (const float*)d_in[14];
    const float* mproj_b = (const float*)d_in[15];
    const float* lnf_w   = (const float*)d_in[16];
    const float* lnf_b   = (const float*)d_in[17];
    float* out = (float*)d_out;

    float *h, *x, *qkv, *att, *mlp;
    cudaGetSymbolAddress((void**)&h,   g_h);
    cudaGetSymbolAddress((void**)&x,   g_x);
    cudaGetSymbolAddress((void**)&qkv, g_qkv);
    cudaGetSymbolAddress((void**)&att, g_att);
    cudaGetSymbolAddress((void**)&mlp, g_mlp);

    cudaFuncSetAttribute(gemm_mma<false, false>,
                         cudaFuncAttributeMaxDynamicSharedMemorySize, GEMM_SMEM);
    cudaFuncSetAttribute(gemm_mma<true, false>,
                         cudaFuncAttributeMaxDynamicSharedMemorySize, GEMM_SMEM);
    cudaFuncSetAttribute(gemm_mma<false, true>,
                         cudaFuncAttributeMaxDynamicSharedMemorySize, GEMM_SMEM);

    embed_kernel<<<MTOK, 256>>>(ids, pos, wte, wpe, h);

    for (int l = 0; l < LL; ++l) {
        ln_kernel<<<MTOK, 256>>>(h, ln1_w + (size_t)l * HH, ln1_b + (size_t)l * HH, x);

        gemm_mma<false, false><<<dim3(QKVW / 128, MTOK / 128), 256, GEMM_SMEM>>>(
            x, cattn_w + (size_t)l * QKVW * HH, cattn_b + (size_t)l * QKVW,
            nullptr, qkv, MTOK, QKVW, HH);

        attn_kernel<<<dim3(SS / 128, NHEAD, BB), 128>>>(qkv, att);

        gemm_mma<true, false><<<dim3(HH / 128, MTOK / 128), 256, GEMM_SMEM>>>(
            att, cproj_w + (size_t)l * HH * HH, cproj_b + (size_t)l * HH,
            h, h, MTOK, HH, HH);

        ln_kernel<<<MTOK, 256>>>(h, ln2_w + (size_t)l * HH, ln2_b + (size_t)l * HH, x);

        gemm_mma<false, true><<<dim3(II / 128, MTOK / 128), 256, GEMM_SMEM>>>(
            x, fc_w + (size_t)l * II * HH, fc_b + (size_t)l * II,
            nullptr, mlp, MTOK, II, HH);

        gemm_mma<true, false><<<dim3(HH / 128, MTOK / 128), 256, GEMM_SMEM>>>(
            mlp, mproj_w + (size_t)l * HH * II, mproj_b + (size_t)l * HH,
            h, h, MTOK, HH, II);
    }

    ln_kernel<<<MTOK, 256>>>(h, lnf_w, lnf_b, out);
}

// round 7
// speedup vs baseline: 1.7805x; 1.2409x over previous
#include <cuda_runtime.h>
#include <cuda_bf16.h>
#include <math.h>
#include <stdint.h>

// ---------------------------------------------------------------------------
// GPT-2-style MQA transformer forward.
//   L=4, H=1024, N=16 heads, D=64, I=4096, B=2, S=2048.
// GEMMs: mma.sync bf16 split-3; hi/lo operands PRE-SPLIT in gmem, cp.async
// 3-stage pipeline. Attention: fp32 SIMT flash kernel (writes hi/lo output).
// ---------------------------------------------------------------------------

#define LL 4
#define HH 1024
#define DD 64
#define NHEAD 16
#define II 4096
#define BB 2
#define SS 2048
#define QKVW (HH + 2 * DD)      // 1152
#define MTOK (BB * SS)          // 4096
#define LN_EPS 1e-5f

typedef __nv_bfloat16 bf16;

// ------------------------- scratch (static device mem) ---------------------
__device__ float g_h  [(size_t)MTOK * HH];     // residual stream (fp32)
__device__ float g_qkv[(size_t)MTOK * QKVW];   // qkv projection (fp32)

// pre-split weights (hi/lo bf16)
__device__ bf16 g_wq_h[(size_t)LL * QKVW * HH], g_wq_l[(size_t)LL * QKVW * HH];
__device__ bf16 g_wc_h[(size_t)LL * HH * HH],   g_wc_l[(size_t)LL * HH * HH];
__device__ bf16 g_wf_h[(size_t)LL * II * HH],   g_wf_l[(size_t)LL * II * HH];
__device__ bf16 g_wm_h[(size_t)LL * HH * II],   g_wm_l[(size_t)LL * HH * II];

// split activations
__device__ bf16 g_xh [(size_t)MTOK * HH], g_xl [(size_t)MTOK * HH];   // LN out
__device__ bf16 g_ath[(size_t)MTOK * HH], g_atl[(size_t)MTOK * HH];   // attn out
__device__ bf16 g_mh [(size_t)MTOK * II], g_ml [(size_t)MTOK * II];   // MLP hidden

// ----------------------------- PTX helpers ---------------------------------
__device__ __forceinline__ uint32_t smem_u32(const void* p) {
    uint32_t a;
    asm("{ .reg .u64 t; cvta.to.shared.u64 t, %1; cvt.u32.u64 %0, t; }"
        : "=r"(a) : "l"(p));
    return a;
}
__device__ __forceinline__ void ldsm4(uint32_t* r, uint32_t addr) {
    asm volatile("ldmatrix.sync.aligned.m8n8.x4.shared.b16 {%0,%1,%2,%3}, [%4];"
        : "=r"(r[0]), "=r"(r[1]), "=r"(r[2]), "=r"(r[3]) : "r"(addr));
}
__device__ __forceinline__ void mma_bf16(float* d, const uint32_t* a,
                                         uint32_t b0, uint32_t b1) {
    asm volatile("mma.sync.aligned.m16n8k16.row.col.f32.bf16.bf16.f32 "
        "{%0,%1,%2,%3}, {%4,%5,%6,%7}, {%8,%9}, {%0,%1,%2,%3};"
        : "+f"(d[0]), "+f"(d[1]), "+f"(d[2]), "+f"(d[3])
        : "r"(a[0]), "r"(a[1]), "r"(a[2]), "r"(a[3]), "r"(b0), "r"(b1));
}
__device__ __forceinline__ void cp16(uint32_t dst, const void* src) {
    asm volatile("cp.async.ca.shared.global [%0], [%1], 16;"
                 :: "r"(dst), "l"(src) : "memory");
}
#define CP_COMMIT() asm volatile("cp.async.commit_group;" ::: "memory")
#define CP_WAIT1()  asm volatile("cp.async.wait_group 1;" ::: "memory")

// pack two fp32 -> bf16x2 hi + bf16x2 lo
__device__ __forceinline__ void split_pair(float x, float y,
                                           uint32_t& hi, uint32_t& lo) {
    bf16 hx = __float2bfloat16(x), hy = __float2bfloat16(y);
    float lx = x - __bfloat162float(hx);
    float ly = y - __bfloat162float(hy);
    bf16 gx = __float2bfloat16(lx), gy = __float2bfloat16(ly);
    hi = (uint32_t)*reinterpret_cast<unsigned short*>(&hx)
       | ((uint32_t)*reinterpret_cast<unsigned short*>(&hy) << 16);
    lo = (uint32_t)*reinterpret_cast<unsigned short*>(&gx)
       | ((uint32_t)*reinterpret_cast<unsigned short*>(&gy) << 16);
}

// --------------------- weight split (fp32 -> bf16 hi/lo) --------------------
__global__ void split_kernel(const float* __restrict__ src,
                             bf16* __restrict__ hi, bf16* __restrict__ lo)
{
    int i = blockIdx.x * blockDim.x + threadIdx.x;   // float4 index
    float4 v = ((const float4*)src)[i];
    uint32_t h01, l01, h23, l23;
    split_pair(v.x, v.y, h01, l01);
    split_pair(v.z, v.w, h23, l23);
    ((uint2*)hi)[i] = make_uint2(h01, h23);
    ((uint2*)lo)[i] = make_uint2(l01, l23);
}

// ----------------------------- embedding -----------------------------------
__global__ void embed_kernel(const int* __restrict__ ids,
                             const int* __restrict__ pos,
                             const float* __restrict__ wte,
                             const float* __restrict__ wpe,
                             float* __restrict__ out)
{
    int row = blockIdx.x;
    int t   = threadIdx.x;
    int id  = ids[row];
    int p   = pos[row];
    const float4* a = (const float4*)(wte + (size_t)id * HH);
    const float4* b = (const float4*)(wpe + (size_t)p  * HH);
    float4 va = a[t], vb = b[t];
    ((float4*)(out + (size_t)row * HH))[t] =
        make_float4(va.x + vb.x, va.y + vb.y, va.z + vb.z, va.w + vb.w);
}

// ----------------------------- layernorm ------------------------------------
// SPLIT=true: write bf16 hi/lo (GEMM input).  SPLIT=false: write fp32 (d_out).
template<bool SPLIT>
__global__ void ln_kernel(const float* __restrict__ x,
                          const float* __restrict__ w,
                          const float* __restrict__ b,
                          bf16* __restrict__ yh, bf16* __restrict__ yl,
                          float* __restrict__ y32)
{
    int row = blockIdx.x;
    int t   = threadIdx.x;
    __shared__ float red[256];

    float4 v = ((const float4*)(x + (size_t)row * HH))[t];
    red[t] = v.x + v.y + v.z + v.w;
    __syncthreads();
    #pragma unroll
    for (int o = 128; o > 0; o >>= 1) { if (t < o) red[t] += red[t + o]; __syncthreads(); }
    float mu = red[0] * (1.0f / HH);
    __syncthreads();

    float dx = v.x - mu, dy = v.y - mu, dz = v.z - mu, dw = v.w - mu;
    red[t] = dx*dx + dy*dy + dz*dz + dw*dw;
    __syncthreads();
    #pragma unroll
    for (int o = 128; o > 0; o >>= 1) { if (t < o) red[t] += red[t + o]; __syncthreads(); }
    float rstd = rsqrtf(red[0] * (1.0f / HH) + LN_EPS);

    float4 ww = ((const float4*)w)[t];
    float4 bb2 = ((const float4*)b)[t];
    float4 o4 = make_float4(dx * rstd * ww.x + bb2.x, dy * rstd * ww.y + bb2.y,
                            dz * rstd * ww.z + bb2.z, dw * rstd * ww.w + bb2.w);
    if (SPLIT) {
        uint32_t h01, l01, h23, l23;
        split_pair(o4.x, o4.y, h01, l01);
        split_pair(o4.z, o4.w, h23, l23);
        ((uint2*)(yh + (size_t)row * HH))[t] = make_uint2(h01, h23);
        ((uint2*)(yl + (size_t)row * HH))[t] = make_uint2(l01, l23);
    } else {
        ((float4*)(y32 + (size_t)row * HH))[t] = o4;
    }
}

// ------------------------- bf16 split-3 MMA GEMM ----------------------------
// C = A @ W^T + bias, operands pre-split bf16 (hi/lo).  M,N%128==0, K%32==0.
// CTA: 128x128, 256 threads, 8 warps (4x2 -> 32x64 per warp).
// 3-stage cp.async pipeline; K chunk = 32.
// MODE 0: C fp32.  MODE 1: C fp32 + resid.  MODE 2: gelu -> Ch/Cl bf16 split.
#define TILE_BYTES 8192                     // 128 x 32 bf16
#define STAGE_BYTES (4 * TILE_BYTES)        // Ah, Al, Wh, Wl
#define GEMM_SMEM (3 * STAGE_BYTES)         // 98304

template<int MODE>
__global__ __launch_bounds__(256, 2)
void gemm_bf16(const bf16* __restrict__ Ah, const bf16* __restrict__ Al,
               const bf16* __restrict__ Wh, const bf16* __restrict__ Wl,
               const float* __restrict__ bias, const float* __restrict__ resid,
               float* __restrict__ C, bf16* __restrict__ Ch, bf16* __restrict__ Cl,
               int M, int Nn, int K)
{
    extern __shared__ char smem[];
    uint32_t sb = smem_u32(smem);

    int tid  = threadIdx.x;
    int lane = tid & 31;
    int wid  = tid >> 5;
    int wm   = wid >> 1;
    int wn   = wid & 1;
    int bm   = blockIdx.y * 128;
    int bn   = blockIdx.x * 128;

    // cp.async fill of one stage (4 tiles x 8KB). 8 x 16B per thread.
    auto fill = [&](int stage, int kb) {
        uint32_t base = sb + stage * STAGE_BYTES;
        #pragma unroll
        for (int s = 0; s < 2; s++) {
            int e   = tid + s * 256;          // 0..511
            int row = e >> 2;
            int seg = e & 3;
            uint32_t off = (uint32_t)row * 64 + ((seg ^ ((row >> 1) & 3)) << 4);
            size_t ga = (size_t)(bm + row) * K + kb + seg * 8;
            size_t gw = (size_t)(bn + row) * K + kb + seg * 8;
            cp16(base + 0 * TILE_BYTES + off, Ah + ga);
            cp16(base + 1 * TILE_BYTES + off, Al + ga);
            cp16(base + 2 * TILE_BYTES + off, Wh + gw);
            cp16(base + 3 * TILE_BYTES + off, Wl + gw);
        }
    };

    // consumer lane geometry (same as validated R6 kernel)
    int maBase = (lane & 7) + ((lane >> 3) & 1) * 8;
    int kAhalf = lane >> 4;
    int nbBase = (lane & 7) + ((lane >> 4) & 1) * 8;
    int kBhalf = (lane >> 3) & 1;

    float acc[2][8][4];
    #pragma unroll
    for (int i = 0; i < 2; i++)
        #pragma unroll
        for (int j = 0; j < 8; j++)
            #pragma unroll
            for (int q = 0; q < 4; q++) acc[i][j][q] = 0.0f;

    const int T = K >> 5;
    fill(0, 0);  CP_COMMIT();
    fill(1, 32); CP_COMMIT();

    for (int t = 0; t < T; ++t) {
        CP_WAIT1();          // group for chunk t complete (<=1 pending)
        __syncthreads();

        int stage = t % 3;
        uint32_t Ab = sb + stage * STAGE_BYTES;
        uint32_t Wb = Ab + 2 * TILE_BYTES;

        #pragma unroll
        for (int kt = 0; kt < 2; ++kt) {
            int kcA = kt * 2 + kAhalf;
            int kcB = kt * 2 + kBhalf;

            uint32_t ah[2][4], al[2][4];
            #pragma unroll
            for (int mi = 0; mi < 2; mi++) {
                int m = wm * 32 + mi * 16 + maBase;
                uint32_t off = (uint32_t)m * 64 + ((kcA ^ ((m >> 1) & 3)) << 4);
                ldsm4(ah[mi], Ab + off);
                ldsm4(al[mi], Ab + TILE_BYTES + off);
            }

            #pragma unroll
            for (int ni = 0; ni < 4; ni++) {
                int n = wn * 64 + ni * 16 + nbBase;
                uint32_t off = (uint32_t)n * 64 + ((kcB ^ ((n >> 1) & 3)) << 4);
                uint32_t bh[4], bl[4];
                ldsm4(bh, Wb + off);
                ldsm4(bl, Wb + TILE_BYTES + off);
                #pragma unroll
                for (int mi = 0; mi < 2; mi++) {
                    mma_bf16(acc[mi][ni * 2 + 0], ah[mi], bh[0], bh[1]);
                    mma_bf16(acc[mi][ni * 2 + 1], ah[mi], bh[2], bh[3]);
                    mma_bf16(acc[mi][ni * 2 + 0], ah[mi], bl[0], bl[1]);
                    mma_bf16(acc[mi][ni * 2 + 1], ah[mi], bl[2], bl[3]);
                    mma_bf16(acc[mi][ni * 2 + 0], al[mi], bh[0], bh[1]);
                    mma_bf16(acc[mi][ni * 2 + 1], al[mi], bh[2], bh[3]);
                }
            }
        }

        if (t + 2 < T) fill((t + 2) % 3, (t + 2) * 32);
        CP_COMMIT();         // keep group numbering aligned (may be empty)
    }

    // ------------------------------ epilogue --------------------------------
    int g     = lane >> 2;
    int cpair = (lane & 3) * 2;
    #pragma unroll
    for (int mi = 0; mi < 2; mi++) {
        #pragma unroll
        for (int j = 0; j < 8; j++) {
            int col = bn + wn * 64 + (j >> 1) * 16 + (j & 1) * 8 + cpair;
            int r0  = bm + wm * 32 + mi * 16 + g;
            float b0 = bias[col], b1 = bias[col + 1];
            #pragma unroll
            for (int hrow = 0; hrow < 2; hrow++) {
                int row = r0 + hrow * 8;
                float v0 = acc[mi][j][hrow * 2 + 0] + b0;
                float v1 = acc[mi][j][hrow * 2 + 1] + b1;
                if (MODE == 2) {
                    v0 = 0.5f * v0 * (1.0f + erff(v0 * 0.70710678118654752f));
                    v1 = 0.5f * v1 * (1.0f + erff(v1 * 0.70710678118654752f));
                    uint32_t hi, lo;
                    split_pair(v0, v1, hi, lo);
                    *(uint32_t*)(Ch + (size_t)row * Nn + col) = hi;
                    *(uint32_t*)(Cl + (size_t)row * Nn + col) = lo;
                } else {
                    if (MODE == 1) {
                        const float* rr = resid + (size_t)row * Nn + col;
                        v0 += rr[0]; v1 += rr[1];
                    }
                    *(float2*)(C + (size_t)row * Nn + col) = make_float2(v0, v1);
                }
            }
        }
    }
}

// ------------------------------ attention -----------------------------------
// MQA causal flash attention, fp32 SIMT; output written as bf16 hi/lo split.
__global__ __launch_bounds__(128)
void attn_kernel(const float* __restrict__ qkv,
                 bf16* __restrict__ oh, bf16* __restrict__ ol)
{
    __shared__ float Ks[64][64];
    __shared__ float Vs[64][64];

    int q0    = blockIdx.x * 128;
    int head  = blockIdx.y;
    int batch = blockIdx.z;
    int tid   = threadIdx.x;
    int qi    = q0 + tid;

    const float* base = qkv + (size_t)batch * SS * QKVW;

    float q[64];
    const float* qrow = base + (size_t)qi * QKVW + head * DD;
    #pragma unroll
    for (int d = 0; d < 64; d += 4) {
        float4 v = *(const float4*)(qrow + d);
        q[d] = v.x * 0.125f; q[d+1] = v.y * 0.125f;
        q[d+2] = v.z * 0.125f; q[d+3] = v.w * 0.125f;
    }

    float acc[64];
    #pragma unroll
    for (int d = 0; d < 64; d++) acc[d] = 0.0f;
    float m = -INFINITY, l = 0.0f;

    int nt = q0 / 64 + 2;
    for (int kt = 0; kt < nt; ++kt) {
        int k0 = kt * 64;
        for (int f = tid; f < 1024; f += 128) {
            int j  = f >> 4;
            int dd = (f & 15) << 2;
            const float* kr = base + (size_t)(k0 + j) * QKVW + HH;
            *(float4*)&Ks[j][dd] = *(const float4*)(kr + dd);
            *(float4*)&Vs[j][dd] = *(const float4*)(kr + DD + dd);
        }
        __syncthreads();

        #pragma unroll 1
        for (int sb2 = 0; sb2 < 64; sb2 += 16) {
            float s[16];
            float mt = -INFINITY;
            #pragma unroll
            for (int jj = 0; jj < 16; ++jj) {
                int j = sb2 + jj;
                float dot = 0.0f;
                #pragma unroll
                for (int d = 0; d < 64; d += 4) {
                    float4 kk = *(const float4*)&Ks[j][d];
                    dot += q[d] * kk.x + q[d+1] * kk.y
                         + q[d+2] * kk.z + q[d+3] * kk.w;
                }
                s[jj] = (k0 + j <= qi) ? dot : -INFINITY;
                mt = fmaxf(mt, s[jj]);
            }
            if (mt != -INFINITY) {
                float mn = fmaxf(m, mt);
                float c  = __expf(m - mn);
                float psum = 0.0f;
                #pragma unroll
                for (int jj = 0; jj < 16; ++jj) {
                    s[jj] = __expf(s[jj] - mn);
                    psum += s[jj];
                }
                l = l * c + psum;
                #pragma unroll
                for (int d = 0; d < 64; d++) acc[d] *= c;
                #pragma unroll
                for (int jj = 0; jj < 16; ++jj) {
                    float pj = s[jj];
                    #pragma unroll
                    for (int d = 0; d < 64; d += 4) {
                        float4 vv = *(const float4*)&Vs[sb2 + jj][d];
                        acc[d]   += pj * vv.x; acc[d+1] += pj * vv.y;
                        acc[d+2] += pj * vv.z; acc[d+3] += pj * vv.w;
                    }
                }
                m = mn;
            }
        }
        __syncthreads();
    }

    float inv = 1.0f / l;
    size_t obase = (size_t)(batch * SS + qi) * HH + head * DD;
    #pragma unroll
    for (int d = 0; d < 64; d += 4) {
        float v0 = acc[d] * inv, v1 = acc[d+1] * inv;
        float v2 = acc[d+2] * inv, v3 = acc[d+3] * inv;
        uint32_t h01, l01, h23, l23;
        split_pair(v0, v1, h01, l01);
        split_pair(v2, v3, h23, l23);
        *(uint2*)(oh + obase + d) = make_uint2(h01, h23);
        *(uint2*)(ol + obase + d) = make_uint2(l01, l23);
    }
}

// ------------------------------- driver -------------------------------------
extern "C" void kernel_launch(void* const* d_in, const int* in_sizes, int n_in,
                              void* d_out, int out_size)
{
    const int*   ids     = (const int*)  d_in[0];
    const int*   pos     = (const int*)  d_in[1];
    const float* wte     = (const float*)d_in[2];
    const float* wpe     = (const float*)d_in[3];
    const float* ln1_w   = (const float*)d_in[4];
    const float* ln1_b   = (const float*)d_in[5];
    const float* cattn_w = (const float*)d_in[6];
    const float* cattn_b = (const float*)d_in[7];
    const float* cproj_w = (const float*)d_in[8];
    const float* cproj_b = (const float*)d_in[9];
    const float* ln2_w   = (const float*)d_in[10];
    const float* ln2_b   = (const float*)d_in[11];
    const float* fc_w    = (const float*)d_in[12];
    const float* fc_b    = (const float*)d_in[13];
    const float* mproj_w = (const float*)d_in[14];
    const float* mproj_b = (const float*)d_in[15];
    const float* lnf_w   = (const float*)d_in[16];
    const float* lnf_b   = (const float*)d_in[17];
    float* out = (float*)d_out;

    float *h, *qkv;
    bf16 *wq_h, *wq_l, *wc_h, *wc_l, *wf_h, *wf_l, *wm_h, *wm_l;
    bf16 *xh, *xl, *ath, *atl, *mh, *ml;
    cudaGetSymbolAddress((void**)&h,    g_h);
    cudaGetSymbolAddress((void**)&qkv,  g_qkv);
    cudaGetSymbolAddress((void**)&wq_h, g_wq_h); cudaGetSymbolAddress((void**)&wq_l, g_wq_l);
    cudaGetSymbolAddress((void**)&wc_h, g_wc_h); cudaGetSymbolAddress((void**)&wc_l, g_wc_l);
    cudaGetSymbolAddress((void**)&wf_h, g_wf_h); cudaGetSymbolAddress((void**)&wf_l, g_wf_l);
    cudaGetSymbolAddress((void**)&wm_h, g_wm_h); cudaGetSymbolAddress((void**)&wm_l, g_wm_l);
    cudaGetSymbolAddress((void**)&xh,  g_xh);  cudaGetSymbolAddress((void**)&xl,  g_xl);
    cudaGetSymbolAddress((void**)&ath, g_ath); cudaGetSymbolAddress((void**)&atl, g_atl);
    cudaGetSymbolAddress((void**)&mh,  g_mh);  cudaGetSymbolAddress((void**)&ml,  g_ml);

    cudaFuncSetAttribute(gemm_bf16<0>, cudaFuncAttributeMaxDynamicSharedMemorySize, GEMM_SMEM);
    cudaFuncSetAttribute(gemm_bf16<1>, cudaFuncAttributeMaxDynamicSharedMemorySize, GEMM_SMEM);
    cudaFuncSetAttribute(gemm_bf16<2>, cudaFuncAttributeMaxDynamicSharedMemorySize, GEMM_SMEM);

    // weight splits (once per launch; ~60us of pure bandwidth)
    split_kernel<<<(LL * QKVW * HH) / 1024, 256>>>(cattn_w, wq_h, wq_l);
    split_kernel<<<(LL * HH * HH)   / 1024, 256>>>(cproj_w, wc_h, wc_l);
    split_kernel<<<(LL * II * HH)   / 1024, 256>>>(fc_w,    wf_h, wf_l);
    split_kernel<<<(LL * HH * II)   / 1024, 256>>>(mproj_w, wm_h, wm_l);

    embed_kernel<<<MTOK, 256>>>(ids, pos, wte, wpe, h);

    for (int l = 0; l < LL; ++l) {
        ln_kernel<true><<<MTOK, 256>>>(h, ln1_w + (size_t)l * HH,
                                       ln1_b + (size_t)l * HH, xh, xl, nullptr);

        gemm_bf16<0><<<dim3(QKVW / 128, MTOK / 128), 256, GEMM_SMEM>>>(
            xh, xl, wq_h + (size_t)l * QKVW * HH, wq_l + (size_t)l * QKVW * HH,
            cattn_b + (size_t)l * QKVW, nullptr, qkv, nullptr, nullptr,
            MTOK, QKVW, HH);

        attn_kernel<<<dim3(SS / 128, NHEAD, BB), 128>>>(qkv, ath, atl);

        gemm_bf16<1><<<dim3(HH / 128, MTOK / 128), 256, GEMM_SMEM>>>(
            ath, atl, wc_h + (size_t)l * HH * HH, wc_l + (size_t)l * HH * HH,
            cproj_b + (size_t)l * HH, h, h, nullptr, nullptr,
            MTOK, HH, HH);

        ln_kernel<true><<<MTOK, 256>>>(h, ln2_w + (size_t)l * HH,
                                       ln2_b + (size_t)l * HH, xh, xl, nullptr);

        gemm_bf16<2><<<dim3(II / 128, MTOK / 128), 256, GEMM_SMEM>>>(
            xh, xl, wf_h + (size_t)l * II * HH, wf_l + (size_t)l * II * HH,
            fc_b + (size_t)l * II, nullptr, nullptr, mh, ml,
            MTOK, II, HH);

        gemm_bf16<1><<<dim3(HH / 128, MTOK / 128), 256, GEMM_SMEM>>>(
            mh, ml, wm_h + (size_t)l * HH * II, wm_l + (size_t)l * HH * II,
            mproj_b + (size_t)l * HH, h, h, nullptr, nullptr,
            MTOK, HH, II);
    }

    ln_kernel<false><<<MTOK, 256>>>(h, lnf_w, lnf_b, nullptr, nullptr, out);
}